// round 10
// baseline (speedup 1.0000x reference)
#include <cuda_runtime.h>
#include <cuda_bf16.h>
#include <cstdint>

#define B_ 1024
#define T_ 200

typedef unsigned long long ull;
typedef unsigned int uint32;

// Scratch for x-projections: [3][T][B][128] fp32 (static device global, allowed).
__device__ float g_proj[(size_t)3 * T_ * B_ * 128];

__device__ __forceinline__ float sigmoidf_(float x) {
    return __fdividef(1.f, 1.f + __expf(-x));
}
__device__ __forceinline__ float tanhf_(float x) {
    x = fminf(fmaxf(x, -15.f), 15.f);
    float e = __expf(2.f * x);
    return __fdividef(e - 1.f, e + 1.f);
}

// ---- packed fp32x2 helpers (sm_100+ PTX, base target) ----
__device__ __forceinline__ ull dup2(float w) {
    ull d; asm("mov.b64 %0, {%1, %1};" : "=l"(d) : "f"(w)); return d;
}
__device__ __forceinline__ ull pack2(float lo, float hi) {
    ull d; asm("mov.b64 %0, {%1, %2};" : "=l"(d) : "f"(lo), "f"(hi)); return d;
}
__device__ __forceinline__ ull fma2(ull a, ull b, ull c) {
    ull d; asm("fma.rn.f32x2 %0, %1, %2, %3;" : "=l"(d) : "l"(a), "l"(b), "l"(c)); return d;
}
__device__ __forceinline__ ull add2(ull a, ull b) {
    ull d; asm("add.rn.f32x2 %0, %1, %2;" : "=l"(d) : "l"(a), "l"(b)); return d;
}
__device__ __forceinline__ void unpack2(ull v, float& lo, float& hi) {
    asm("mov.b64 {%0, %1}, %2;" : "=f"(lo), "=f"(hi) : "l"(v));
}

__device__ __forceinline__ uint32 pk_bf16(float a, float b) {
    return (uint32)__bfloat16_as_ushort(__float2bfloat16(a)) |
           ((uint32)__bfloat16_as_ushort(__float2bfloat16(b)) << 16);
}
__device__ __forceinline__ void mma_bf16(float& c0, float& c1, float& c2, float& c3,
                                         uint32 a0, uint32 a1, uint32 a2, uint32 a3,
                                         uint32 b0, uint32 b1) {
    asm volatile(
        "mma.sync.aligned.m16n8k16.row.col.f32.bf16.bf16.f32 "
        "{%0,%1,%2,%3}, {%4,%5,%6,%7}, {%8,%9}, {%0,%1,%2,%3};"
        : "+f"(c0), "+f"(c1), "+f"(c2), "+f"(c3)
        : "r"(a0), "r"(a1), "r"(a2), "r"(a3), "r"(b0), "r"(b1));
}

// ---------------------------------------------------------------------------
// Pass 1 (HMMA): g_proj[m][.][.][:] = X @ Wm_top via bf16-split mma.sync.
// (unchanged from round 8/9 — ~243-246us, rel_err 4.9e-6)
// ---------------------------------------------------------------------------
#define SW_OFF(row, word) (((uint32)(row) << 8) + ((((word) ^ (((row) & 7) << 2)) & 63) << 2))
__global__ __launch_bounds__(256, 1) void proj_kernel(
    const float* __restrict__ x,
    const float* __restrict__ Wu, const float* __restrict__ Wr,
    const float* __restrict__ Wc)
{
    extern __shared__ char smc[];
    char* sXh = smc + 196608;
    char* sXl = smc + 204800;
    const int tid  = threadIdx.x;
    const int w    = tid >> 5;
    const int lane = tid & 31;
    const int gr   = lane >> 2;
    const int gc   = lane & 3;
    const int wr   = w >> 2;
    const int wc   = w & 3;
    const int r0   = wr * 16;

    {
        const float* Ws[3] = {Wu, Wr, Wc};
        for (int m = 0; m < 3; ++m) {
            char* hb = smc + m * 32768;
            char* lb = smc + (3 + m) * 32768;
            for (int idx = tid; idx < 16384; idx += 256) {
                int k = idx >> 7, j = idx & 127;
                float v = Ws[m][idx];
                __nv_bfloat16 hbf = __float2bfloat16(v);
                float lres = v - __bfloat162float(hbf);
                uint32 off = SW_OFF(j, k >> 1) + (k & 1) * 2;
                *(__nv_bfloat16*)(hb + off) = hbf;
                *(__nv_bfloat16*)(lb + off) = __float2bfloat16(lres);
            }
        }
    }

    const float4* x4 = (const float4*)x;
    const int ntiles = (B_ * T_) / 32;

    float4 xreg[4];
    int tile = blockIdx.x;
    if (tile < ntiles) {
#pragma unroll
        for (int c = 0; c < 4; ++c) xreg[c] = x4[(size_t)tile * 1024 + tid + c * 256];
    }

    for (; tile < ntiles; tile += gridDim.x) {
        __syncthreads();
#pragma unroll
        for (int c = 0; c < 4; ++c) {
            int f = tid + c * 256;
            int r = f >> 5;
            int wd = (f & 31) * 2;
            float4 v = xreg[c];
            uint32 off = SW_OFF(r, wd);
            *(ull*)(sXh + off) = (ull)pk_bf16(v.x, v.y) | ((ull)pk_bf16(v.z, v.w) << 32);
            float lx = v.x - __bfloat162float(__float2bfloat16(v.x));
            float ly = v.y - __bfloat162float(__float2bfloat16(v.y));
            float lz = v.z - __bfloat162float(__float2bfloat16(v.z));
            float lw = v.w - __bfloat162float(__float2bfloat16(v.w));
            *(ull*)(sXl + off) = (ull)pk_bf16(lx, ly) | ((ull)pk_bf16(lz, lw) << 32);
        }
        __syncthreads();

        int ntile = tile + gridDim.x;
        if (ntile < ntiles) {
#pragma unroll
            for (int c = 0; c < 4; ++c) xreg[c] = x4[(size_t)ntile * 1024 + tid + c * 256];
        }

        float C[12][4];
#pragma unroll
        for (int n = 0; n < 12; ++n)
#pragma unroll
            for (int i = 0; i < 4; ++i) C[n][i] = 0.f;

#pragma unroll
        for (int kt = 0; kt < 8; ++kt) {
            const int kw = kt * 8 + gc;
            const uint32 oA0 = SW_OFF(r0 + gr,     kw);
            const uint32 oA1 = SW_OFF(r0 + gr + 8, kw);
            const uint32 oA2 = SW_OFF(r0 + gr,     kw + 4);
            const uint32 oA3 = SW_OFF(r0 + gr + 8, kw + 4);
            uint32 ah0 = *(const uint32*)(sXh + oA0);
            uint32 ah1 = *(const uint32*)(sXh + oA1);
            uint32 ah2 = *(const uint32*)(sXh + oA2);
            uint32 ah3 = *(const uint32*)(sXh + oA3);
            uint32 al0 = *(const uint32*)(sXl + oA0);
            uint32 al1 = *(const uint32*)(sXl + oA1);
            uint32 al2 = *(const uint32*)(sXl + oA2);
            uint32 al3 = *(const uint32*)(sXl + oA3);
#pragma unroll
            for (int nt = 0; nt < 12; ++nt) {
                int n0 = wc * 96 + nt * 8;
                int m  = n0 >> 7;
                int jb = (n0 & 127) + gr;
                const char* bh = smc + m * 32768;
                const char* bl = smc + (3 + m) * 32768;
                uint32 oB0 = SW_OFF(jb, kw);
                uint32 oB1 = SW_OFF(jb, kw + 4);
                uint32 bh0 = *(const uint32*)(bh + oB0);
                uint32 bh1 = *(const uint32*)(bh + oB1);
                uint32 bl0 = *(const uint32*)(bl + oB0);
                uint32 bl1 = *(const uint32*)(bl + oB1);
                mma_bf16(C[nt][0], C[nt][1], C[nt][2], C[nt][3],
                         ah0, ah1, ah2, ah3, bh0, bh1);
                mma_bf16(C[nt][0], C[nt][1], C[nt][2], C[nt][3],
                         ah0, ah1, ah2, ah3, bl0, bl1);
                mma_bf16(C[nt][0], C[nt][1], C[nt][2], C[nt][3],
                         al0, al1, al2, al3, bh0, bh1);
            }
        }

        const int ridA = tile * 32 + r0 + gr;
        const int ridB = ridA + 8;
        const int bA = ridA / T_, tA = ridA - bA * T_;
        const int bB = ridB / T_, tB = ridB - bB * T_;
#pragma unroll
        for (int nt = 0; nt < 12; ++nt) {
            int cgl = wc * 96 + nt * 8 + gc * 2;
            int m = cgl >> 7, j = cgl & 127;
            float* dA = g_proj + ((size_t)(m * T_ + tA) * B_ + bA) * 128 + j;
            float* dB = g_proj + ((size_t)(m * T_ + tB) * B_ + bB) * 128 + j;
            *(float2*)dA = make_float2(C[nt][0], C[nt][1]);
            *(float2*)dB = make_float2(C[nt][2], C[nt][3]);
        }
    }
}

// ---------------------------------------------------------------------------
// Pass 2: persistent recurrence. 128 CTAs x 8 batch rows, 256 threads.
// Thread (kh, j): kh = tid>>7, j = output column. Finalizes rows rb..rb+3
// (rb = kh*4).
// Phase A: k-half over all 8 rows (Wur packed ull from smem), one exchange.
// Phase B: FULL k over own 4 rows only, Wc register-resident -> NO exchange.
// 3 syncs/step (was 4), no phase-B reduction traffic.
// ---------------------------------------------------------------------------
__global__ __launch_bounds__(256, 1) void rec_kernel(
    const float* __restrict__ att,
    const void* __restrict__ slen_raw,
    const float* __restrict__ Wu, const float* __restrict__ Wr,
    const float* __restrict__ Wc,
    float* __restrict__ out)
{
    extern __shared__ float sm[];
    ull*   sWur = (ull*)sm;             // [128 k][128 j] (wu,wr)  131072 B
    float* shv  = sm + 32768;           // h:   [128 k][8 rows]      4096 B
    float* srh  = sm + 33792;           // r*h: [128 k][8 rows]      4096 B
    ull*   red  = (ull*)(sm + 34816);   // A-exchange [2 kh][128 j][4]  8192 B
    __shared__ int s_is64;
    const int tid = threadIdx.x;
    const int kh  = tid >> 7;           // k-half 0/1
    const int j   = tid & 127;
    const int k0  = kh * 64;
    const int b0  = blockIdx.x * 8;
    const int rb  = kh * 4;             // this thread's finalize rows rb..rb+3

    // Wc bottom half fully register-resident (128 floats / thread).
    float wc_reg[128];
#pragma unroll
    for (int kk = 0; kk < 128; ++kk) wc_reg[kk] = Wc[16384 + kk * 128 + j];

    for (int i = tid; i < 16384; i += 256)
        sWur[i] = pack2(Wu[16384 + i], Wr[16384 + i]);    // bottom halves
    for (int i = tid; i < 1024; i += 256) shv[i] = 0.f;
    if (tid == 0) {
        const int* a = (const int*)slen_raw;    // int64 detection via high words
        s_is64 = (a[1] == 0 && a[3] == 0 && a[5] == 0 && a[7] == 0) ? 1 : 0;
    }
    __syncthreads();

    int sl[4];
    if (s_is64) {
        const long long* p = (const long long*)slen_raw;
#pragma unroll
        for (int r = 0; r < 4; ++r) sl[r] = (int)p[b0 + rb + r];
    } else {
        const int* p = (const int*)slen_raw;
#pragma unroll
        for (int r = 0; r < 4; ++r) sl[r] = p[b0 + rb + r];
    }

    float h_own[4] = {0.f, 0.f, 0.f, 0.f};
    ull* myred = red + (size_t)kh * 512 + (size_t)j * 4;
    const ull* otred = red + (size_t)(kh ^ 1) * 512 + (size_t)j * 4;

    for (int t = 0; t < T_; ++t) {
        // Front-issue globals for this thread's 4 finalize rows.
        float xu[4], xr[4], xc[4], av[4];
#pragma unroll
        for (int r = 0; r < 4; ++r) {
            int row = b0 + rb + r;
            xu[r] = g_proj[((size_t)(0 * T_ + t) * B_ + row) * 128 + j];
            xr[r] = g_proj[((size_t)(1 * T_ + t) * B_ + row) * 128 + j];
            xc[r] = g_proj[((size_t)(2 * T_ + t) * B_ + row) * 128 + j];
            av[r] = att[(size_t)row * T_ + t];
        }

        // ---- phase A: partial u_pre / r_pre over k-half, all 8 rows ----
        ull au0 = 0, au1 = 0, au2 = 0, au3 = 0;
        ull ar0 = 0, ar1 = 0, ar2 = 0, ar3 = 0;
#pragma unroll
        for (int kk = 0; kk < 64; ++kk) {
            int k = k0 + kk;
            ull wpair = sWur[k * 128 + j];
            float wuf, wrf; unpack2(wpair, wuf, wrf);
            ull wu2 = dup2(wuf), wr2 = dup2(wrf);
            const float* hk = shv + k * 8;
            ulonglong2 hA = *(const ulonglong2*)(hk);
            ulonglong2 hB = *(const ulonglong2*)(hk + 4);
            au0 = fma2(hA.x, wu2, au0); au1 = fma2(hA.y, wu2, au1);
            au2 = fma2(hB.x, wu2, au2); au3 = fma2(hB.y, wu2, au3);
            ar0 = fma2(hA.x, wr2, ar0); ar1 = fma2(hA.y, wr2, ar1);
            ar2 = fma2(hB.x, wr2, ar2); ar3 = fma2(hB.y, wr2, ar3);
        }
        // Exchange the half this thread does NOT finalize.
        {
            ulonglong2* rd = (ulonglong2*)myred;
            if (kh == 0) { rd[0] = make_ulonglong2(au2, au3); rd[1] = make_ulonglong2(ar2, ar3); }
            else         { rd[0] = make_ulonglong2(au0, au1); rd[1] = make_ulonglong2(ar0, ar1); }
        }
        __syncthreads();

        float u4[4];
        {
            const ulonglong2* rd = (const ulonglong2*)otred;
            ulonglong2 pu = rd[0], pr = rd[1];
            ull fu0, fu1, fr0, fr1;
            if (kh == 0) {
                fu0 = add2(au0, pu.x); fu1 = add2(au1, pu.y);
                fr0 = add2(ar0, pr.x); fr1 = add2(ar1, pr.y);
            } else {
                fu0 = add2(au2, pu.x); fu1 = add2(au3, pu.y);
                fr0 = add2(ar2, pr.x); fr1 = add2(ar3, pr.y);
            }
            float up[4], rp[4];
            unpack2(fu0, up[0], up[1]); unpack2(fu1, up[2], up[3]);
            unpack2(fr0, rp[0], rp[1]); unpack2(fr1, rp[2], rp[3]);
            float s[4];
#pragma unroll
            for (int r = 0; r < 4; ++r) {
                u4[r] = sigmoidf_(up[r] + xu[r]);
                s[r]  = sigmoidf_(rp[r] + xr[r]) * h_own[r];
            }
            *(float4*)(srh + j * 8 + rb) = make_float4(s[0], s[1], s[2], s[3]);
        }
        __syncthreads();   // srh ready

        // ---- phase B: FULL k over own 4 rows; Wc in registers ----
        ull ac0 = 0, ac1 = 0;
#pragma unroll
        for (int kk = 0; kk < 128; ++kk) {
            ull wc2 = dup2(wc_reg[kk]);
            ulonglong2 sv = *(const ulonglong2*)(srh + kk * 8 + rb);
            ac0 = fma2(sv.x, wc2, ac0);
            ac1 = fma2(sv.y, wc2, ac1);
        }
        {
            float cp[4];
            unpack2(ac0, cp[0], cp[1]); unpack2(ac1, cp[2], cp[3]);
#pragma unroll
            for (int r = 0; r < 4; ++r) {
                float ht   = tanhf_(cp[r] + xc[r]);
                float ut   = u4[r] * av[r];
                float hold = h_own[r];
                float hn   = hold + ut * (ht - hold);
                float hnew = (t < sl[r]) ? hn : hold;
                h_own[r]   = hnew;
                out[((size_t)(b0 + rb + r) * T_ + t) * 128 + j] = hnew;
            }
            *(float4*)(shv + j * 8 + rb) = make_float4(h_own[0], h_own[1], h_own[2], h_own[3]);
        }
        __syncthreads();   // new h visible for next step
    }
}

// ---------------------------------------------------------------------------
extern "C" void kernel_launch(void* const* d_in, const int* in_sizes, int n_in,
                              void* d_out, int out_size)
{
    // Resolve inputs by element count (robust to metadata ordering).
    int iSeq = -1, iLen = -1, iAtt = -1, iW[3] = {-1, -1, -1};
    int nw = 0;
    for (int i = 0; i < n_in; ++i) {
        int s = in_sizes[i];
        if      (s == 26214400) iSeq = i;
        else if (s == 1024)     iLen = i;
        else if (s == 204800)   iAtt = i;
        else if (s == 32768 && nw < 3) iW[nw++] = i;
    }
    if (iSeq < 0 || iLen < 0 || iAtt < 0 || nw != 3) {
        iSeq = 0; iLen = 1; iAtt = 2; iW[0] = 3; iW[1] = 4; iW[2] = 5;
    }
    int iWu, iWr, iWc;
    if (iW[0] < iSeq) { iWc = iW[0]; iWr = iW[1]; iWu = iW[2]; }  // alphabetical
    else              { iWu = iW[0]; iWr = iW[1]; iWc = iW[2]; }  // insertion

    const float* seq_emb = (const float*)d_in[iSeq];
    const void*  slen    = d_in[iLen];
    const float* att     = (const float*)d_in[iAtt];
    const float* Wu      = (const float*)d_in[iWu];
    const float* Wr      = (const float*)d_in[iWr];
    const float* Wc      = (const float*)d_in[iWc];
    float*       out     = (float*)d_out;

    const int smem1 = 6 * 32768 + 2 * 8192;        // 212992 B
    const int smem2 = 36864 * (int)sizeof(float);  // 147456 B
    cudaFuncSetAttribute(proj_kernel, cudaFuncAttributeMaxDynamicSharedMemorySize, smem1);
    cudaFuncSetAttribute(rec_kernel,  cudaFuncAttributeMaxDynamicSharedMemorySize, smem2);

    proj_kernel<<<148, 256, smem1>>>(seq_emb, Wu, Wr, Wc);
    rec_kernel<<<128, 256, smem2>>>(att, slen, Wu, Wr, Wc, out);
}

// round 11
// speedup vs baseline: 1.2854x; 1.2854x over previous
#include <cuda_runtime.h>
#include <cuda_bf16.h>
#include <cstdint>

#define B_ 1024
#define T_ 200

typedef unsigned long long ull;
typedef unsigned int uint32;

// Scratch for x-projections: [3][T][B][128] fp32 (static device global, allowed).
__device__ float g_proj[(size_t)3 * T_ * B_ * 128];

__device__ __forceinline__ float sigmoidf_(float x) {
    return __fdividef(1.f, 1.f + __expf(-x));
}
__device__ __forceinline__ float tanhf_(float x) {
    x = fminf(fmaxf(x, -15.f), 15.f);
    float e = __expf(2.f * x);
    return __fdividef(e - 1.f, e + 1.f);
}

__device__ __forceinline__ uint32 pk_bf16(float a, float b) {
    return (uint32)__bfloat16_as_ushort(__float2bfloat16(a)) |
           ((uint32)__bfloat16_as_ushort(__float2bfloat16(b)) << 16);
}
__device__ __forceinline__ float bf16hi_res(float v, float& hi) {
    __nv_bfloat16 h = __float2bfloat16(v);
    hi = __bfloat162float(h);
    return v - hi;
}
__device__ __forceinline__ void mma_bf16(float& c0, float& c1, float& c2, float& c3,
                                         uint32 a0, uint32 a1, uint32 a2, uint32 a3,
                                         uint32 b0, uint32 b1) {
    asm volatile(
        "mma.sync.aligned.m16n8k16.row.col.f32.bf16.bf16.f32 "
        "{%0,%1,%2,%3}, {%4,%5,%6,%7}, {%8,%9}, {%0,%1,%2,%3};"
        : "+f"(c0), "+f"(c1), "+f"(c2), "+f"(c3)
        : "r"(a0), "r"(a1), "r"(a2), "r"(a3), "r"(b0), "r"(b1));
}

// ---------------------------------------------------------------------------
// Pass 1 (HMMA): g_proj[m][.][.][:] = X @ Wm_top via bf16-split mma.sync.
// (unchanged from rounds 8-10 — ~246us, rel_err 4.9e-6)
// ---------------------------------------------------------------------------
#define SW_OFF(row, word) (((uint32)(row) << 8) + ((((word) ^ (((row) & 7) << 2)) & 63) << 2))
__global__ __launch_bounds__(256, 1) void proj_kernel(
    const float* __restrict__ x,
    const float* __restrict__ Wu, const float* __restrict__ Wr,
    const float* __restrict__ Wc)
{
    extern __shared__ char smc[];
    char* sXh = smc + 196608;
    char* sXl = smc + 204800;
    const int tid  = threadIdx.x;
    const int w    = tid >> 5;
    const int lane = tid & 31;
    const int gr   = lane >> 2;
    const int gc   = lane & 3;
    const int wr   = w >> 2;
    const int wc   = w & 3;
    const int r0   = wr * 16;

    {
        const float* Ws[3] = {Wu, Wr, Wc};
        for (int m = 0; m < 3; ++m) {
            char* hb = smc + m * 32768;
            char* lb = smc + (3 + m) * 32768;
            for (int idx = tid; idx < 16384; idx += 256) {
                int k = idx >> 7, j = idx & 127;
                float v = Ws[m][idx];
                __nv_bfloat16 hbf = __float2bfloat16(v);
                float lres = v - __bfloat162float(hbf);
                uint32 off = SW_OFF(j, k >> 1) + (k & 1) * 2;
                *(__nv_bfloat16*)(hb + off) = hbf;
                *(__nv_bfloat16*)(lb + off) = __float2bfloat16(lres);
            }
        }
    }

    const float4* x4 = (const float4*)x;
    const int ntiles = (B_ * T_) / 32;

    float4 xreg[4];
    int tile = blockIdx.x;
    if (tile < ntiles) {
#pragma unroll
        for (int c = 0; c < 4; ++c) xreg[c] = x4[(size_t)tile * 1024 + tid + c * 256];
    }

    for (; tile < ntiles; tile += gridDim.x) {
        __syncthreads();
#pragma unroll
        for (int c = 0; c < 4; ++c) {
            int f = tid + c * 256;
            int r = f >> 5;
            int wd = (f & 31) * 2;
            float4 v = xreg[c];
            uint32 off = SW_OFF(r, wd);
            *(ull*)(sXh + off) = (ull)pk_bf16(v.x, v.y) | ((ull)pk_bf16(v.z, v.w) << 32);
            float lx = v.x - __bfloat162float(__float2bfloat16(v.x));
            float ly = v.y - __bfloat162float(__float2bfloat16(v.y));
            float lz = v.z - __bfloat162float(__float2bfloat16(v.z));
            float lw = v.w - __bfloat162float(__float2bfloat16(v.w));
            *(ull*)(sXl + off) = (ull)pk_bf16(lx, ly) | ((ull)pk_bf16(lz, lw) << 32);
        }
        __syncthreads();

        int ntile = tile + gridDim.x;
        if (ntile < ntiles) {
#pragma unroll
            for (int c = 0; c < 4; ++c) xreg[c] = x4[(size_t)ntile * 1024 + tid + c * 256];
        }

        float C[12][4];
#pragma unroll
        for (int n = 0; n < 12; ++n)
#pragma unroll
            for (int i = 0; i < 4; ++i) C[n][i] = 0.f;

#pragma unroll
        for (int kt = 0; kt < 8; ++kt) {
            const int kw = kt * 8 + gc;
            const uint32 oA0 = SW_OFF(r0 + gr,     kw);
            const uint32 oA1 = SW_OFF(r0 + gr + 8, kw);
            const uint32 oA2 = SW_OFF(r0 + gr,     kw + 4);
            const uint32 oA3 = SW_OFF(r0 + gr + 8, kw + 4);
            uint32 ah0 = *(const uint32*)(sXh + oA0);
            uint32 ah1 = *(const uint32*)(sXh + oA1);
            uint32 ah2 = *(const uint32*)(sXh + oA2);
            uint32 ah3 = *(const uint32*)(sXh + oA3);
            uint32 al0 = *(const uint32*)(sXl + oA0);
            uint32 al1 = *(const uint32*)(sXl + oA1);
            uint32 al2 = *(const uint32*)(sXl + oA2);
            uint32 al3 = *(const uint32*)(sXl + oA3);
#pragma unroll
            for (int nt = 0; nt < 12; ++nt) {
                int n0 = wc * 96 + nt * 8;
                int m  = n0 >> 7;
                int jb = (n0 & 127) + gr;
                const char* bh = smc + m * 32768;
                const char* bl = smc + (3 + m) * 32768;
                uint32 oB0 = SW_OFF(jb, kw);
                uint32 oB1 = SW_OFF(jb, kw + 4);
                uint32 bh0 = *(const uint32*)(bh + oB0);
                uint32 bh1 = *(const uint32*)(bh + oB1);
                uint32 bl0 = *(const uint32*)(bl + oB0);
                uint32 bl1 = *(const uint32*)(bl + oB1);
                mma_bf16(C[nt][0], C[nt][1], C[nt][2], C[nt][3],
                         ah0, ah1, ah2, ah3, bh0, bh1);
                mma_bf16(C[nt][0], C[nt][1], C[nt][2], C[nt][3],
                         ah0, ah1, ah2, ah3, bl0, bl1);
                mma_bf16(C[nt][0], C[nt][1], C[nt][2], C[nt][3],
                         al0, al1, al2, al3, bh0, bh1);
            }
        }

        const int ridA = tile * 32 + r0 + gr;
        const int ridB = ridA + 8;
        const int bA = ridA / T_, tA = ridA - bA * T_;
        const int bB = ridB / T_, tB = ridB - bB * T_;
#pragma unroll
        for (int nt = 0; nt < 12; ++nt) {
            int cgl = wc * 96 + nt * 8 + gc * 2;
            int m = cgl >> 7, j = cgl & 127;
            float* dA = g_proj + ((size_t)(m * T_ + tA) * B_ + bA) * 128 + j;
            float* dB = g_proj + ((size_t)(m * T_ + tB) * B_ + bB) * 128 + j;
            *(float2*)dA = make_float2(C[nt][0], C[nt][1]);
            *(float2*)dB = make_float2(C[nt][2], C[nt][3]);
        }
    }
}

// ---------------------------------------------------------------------------
// Pass 2 (HMMA recurrence): 128 CTAs x 8 batch rows, 256 threads (8 warps).
// Warp w owns output cols [16w, 16w+16). Per step:
//   gates:  D[8,16]x2 = h[8,128] @ {Wu,Wr}_bot  (4 ntiles x 8 kt x 3 passes)
//   cand :  D[8,16]   = (r*h)    @ Wc_bot       (2 ntiles x 8 kt x 3 passes)
// bf16-split (hi*hi + hi*lo + lo*hi), f32 accum. W-hi frags in registers,
// W-lo frags in smem. h lives in registers; its bf16 hi/lo A-fragments for
// k-tile w are exactly the D-fragment values warp w produces -> STS.128.
// 2 barriers per step, no partial-sum exchange.
// ---------------------------------------------------------------------------
__global__ __launch_bounds__(256, 1) void rec_kernel(
    const float* __restrict__ att,
    const void* __restrict__ slen_raw,
    const float* __restrict__ Wu, const float* __restrict__ Wr,
    const float* __restrict__ Wc,
    float* __restrict__ out)
{
    extern __shared__ char smr[];
    uint32* hfrag = (uint32*)smr;             // [8 kt][32 lane][4 u32]  4096 B
    uint32* sfrag = (uint32*)(smr + 4096);    // [8 kt][32 lane][4 u32]  4096 B
    uint32* blo   = (uint32*)(smr + 8192);    // [48 g][8 kt][32 lane][2 u32] 98304 B
    __shared__ int s_is64;

    const int tid  = threadIdx.x;
    const int w    = tid >> 5;
    const int lane = tid & 31;
    const int qr   = lane >> 2;               // frag row / n-within-tile 0..7
    const int qc   = lane & 3;
    const int row  = blockIdx.x * 8 + qr;     // global batch row
    const int colA = w * 16 + qc * 2;         // output cols colA,colA+1
    const int colB = colA + 8;                //             colB,colB+1

    // ---- build B fragments: hi -> registers, lo -> smem ----
    uint32 bhi[6][8][2];
#pragma unroll
    for (int f = 0; f < 6; ++f) {
        const float* Wsrc = (f < 2) ? Wu : (f < 4 ? Wr : Wc);
        const int n = w * 16 + (f & 1) * 8 + qr;
#pragma unroll
        for (int kt = 0; kt < 8; ++kt) {
            int k = kt * 16 + qc * 2;
            float h00, h01, h10, h11;
            float l00 = bf16hi_res(Wsrc[16384 + k * 128 + n], h00);
            float l01 = bf16hi_res(Wsrc[16384 + (k + 1) * 128 + n], h01);
            float l10 = bf16hi_res(Wsrc[16384 + (k + 8) * 128 + n], h10);
            float l11 = bf16hi_res(Wsrc[16384 + (k + 9) * 128 + n], h11);
            bhi[f][kt][0] = pk_bf16(h00, h01);
            bhi[f][kt][1] = pk_bf16(h10, h11);
            uint32* dst = blo + (((w * 6 + f) * 8 + kt) * 32 + lane) * 2;
            dst[0] = pk_bf16(l00, l01);
            dst[1] = pk_bf16(l10, l11);
        }
    }
    // zero h fragments
    for (int i = tid; i < 1024; i += 256) hfrag[i] = 0u;
    if (tid == 0) {
        const int* a = (const int*)slen_raw;   // int64 detection via high words
        s_is64 = (a[1] == 0 && a[3] == 0 && a[5] == 0 && a[7] == 0) ? 1 : 0;
    }
    __syncthreads();

    int sl;
    if (s_is64) sl = (int)((const long long*)slen_raw)[row];
    else        sl = ((const int*)slen_raw)[row];

    float h0 = 0.f, h1 = 0.f, h2 = 0.f, h3 = 0.f;  // h at (row,colA..+1),(row,colB..+1)
    const uint32 z = 0u;

    for (int t = 0; t < T_; ++t) {
        // ---- phase 1: gate MMAs (u: f0,f1 | r: f2,f3) ----
        float Dg[4][4];
#pragma unroll
        for (int f = 0; f < 4; ++f)
#pragma unroll
            for (int i = 0; i < 4; ++i) Dg[f][i] = 0.f;

#pragma unroll
        for (int kt = 0; kt < 8; ++kt) {
            uint4 af = *(const uint4*)(hfrag + (kt * 32 + lane) * 4);  // a0h,a2h,a0l,a2l
#pragma unroll
            for (int f = 0; f < 4; ++f) {
                const uint32* bl = blo + (((w * 6 + f) * 8 + kt) * 32 + lane) * 2;
                uint32 bl0 = bl[0], bl1 = bl[1];
                mma_bf16(Dg[f][0], Dg[f][1], Dg[f][2], Dg[f][3],
                         af.x, z, af.y, z, bhi[f][kt][0], bhi[f][kt][1]);
                mma_bf16(Dg[f][0], Dg[f][1], Dg[f][2], Dg[f][3],
                         af.x, z, af.y, z, bl0, bl1);
                mma_bf16(Dg[f][0], Dg[f][1], Dg[f][2], Dg[f][3],
                         af.z, z, af.w, z, bhi[f][kt][0], bhi[f][kt][1]);
            }
        }

        // ---- gate finalize: u = sig(u_pre+xu); s = sig(r_pre+xr)*h ----
        const float* gp = g_proj + (size_t)t * B_ * 128 + (size_t)row * 128;
        float2 xuA = *(const float2*)(gp + colA);
        float2 xuB = *(const float2*)(gp + colB);
        float2 xrA = *(const float2*)(gp + (size_t)T_ * B_ * 128 + colA);
        float2 xrB = *(const float2*)(gp + (size_t)T_ * B_ * 128 + colB);
        float uA0 = sigmoidf_(Dg[0][0] + xuA.x);
        float uA1 = sigmoidf_(Dg[0][1] + xuA.y);
        float uB0 = sigmoidf_(Dg[1][0] + xuB.x);
        float uB1 = sigmoidf_(Dg[1][1] + xuB.y);
        float sA0 = sigmoidf_(Dg[2][0] + xrA.x) * h0;
        float sA1 = sigmoidf_(Dg[2][1] + xrA.y) * h1;
        float sB0 = sigmoidf_(Dg[3][0] + xrB.x) * h2;
        float sB1 = sigmoidf_(Dg[3][1] + xrB.y) * h3;
        {
            float hA0, hA1, hB0, hB1;
            float lA0 = bf16hi_res(sA0, hA0), lA1 = bf16hi_res(sA1, hA1);
            float lB0 = bf16hi_res(sB0, hB0), lB1 = bf16hi_res(sB1, hB1);
            uint4 sf;
            sf.x = pk_bf16(hA0, hA1); sf.y = pk_bf16(hB0, hB1);
            sf.z = pk_bf16(lA0, lA1); sf.w = pk_bf16(lB0, lB1);
            *(uint4*)(sfrag + (w * 32 + lane) * 4) = sf;
        }
        __syncthreads();   // s-fragments ready

        // ---- phase 2: candidate MMAs (f4,f5) ----
        float Dc[2][4];
#pragma unroll
        for (int f = 0; f < 2; ++f)
#pragma unroll
            for (int i = 0; i < 4; ++i) Dc[f][i] = 0.f;

#pragma unroll
        for (int kt = 0; kt < 8; ++kt) {
            uint4 af = *(const uint4*)(sfrag + (kt * 32 + lane) * 4);
#pragma unroll
            for (int f = 0; f < 2; ++f) {
                const uint32* bl = blo + (((w * 6 + 4 + f) * 8 + kt) * 32 + lane) * 2;
                uint32 bl0 = bl[0], bl1 = bl[1];
                mma_bf16(Dc[f][0], Dc[f][1], Dc[f][2], Dc[f][3],
                         af.x, z, af.y, z, bhi[4 + f][kt][0], bhi[4 + f][kt][1]);
                mma_bf16(Dc[f][0], Dc[f][1], Dc[f][2], Dc[f][3],
                         af.x, z, af.y, z, bl0, bl1);
                mma_bf16(Dc[f][0], Dc[f][1], Dc[f][2], Dc[f][3],
                         af.z, z, af.w, z, bhi[4 + f][kt][0], bhi[4 + f][kt][1]);
            }
        }

        // ---- update ----
        float2 xcA = *(const float2*)(gp + (size_t)2 * T_ * B_ * 128 + colA);
        float2 xcB = *(const float2*)(gp + (size_t)2 * T_ * B_ * 128 + colB);
        float av = att[(size_t)row * T_ + t];
        bool live = (t < sl);
        {
            float htA0 = tanhf_(Dc[0][0] + xcA.x);
            float htA1 = tanhf_(Dc[0][1] + xcA.y);
            float htB0 = tanhf_(Dc[1][0] + xcB.x);
            float htB1 = tanhf_(Dc[1][1] + xcB.y);
            float n0 = h0 + uA0 * av * (htA0 - h0);
            float n1 = h1 + uA1 * av * (htA1 - h1);
            float n2 = h2 + uB0 * av * (htB0 - h2);
            float n3 = h3 + uB1 * av * (htB1 - h3);
            h0 = live ? n0 : h0;
            h1 = live ? n1 : h1;
            h2 = live ? n2 : h2;
            h3 = live ? n3 : h3;
        }
        float* op = out + ((size_t)row * T_ + t) * 128;
        *(float2*)(op + colA) = make_float2(h0, h1);
        *(float2*)(op + colB) = make_float2(h2, h3);
        {
            float hA0, hA1, hB0, hB1;
            float lA0 = bf16hi_res(h0, hA0), lA1 = bf16hi_res(h1, hA1);
            float lB0 = bf16hi_res(h2, hB0), lB1 = bf16hi_res(h3, hB1);
            uint4 hf;
            hf.x = pk_bf16(hA0, hA1); hf.y = pk_bf16(hB0, hB1);
            hf.z = pk_bf16(lA0, lA1); hf.w = pk_bf16(lB0, lB1);
            *(uint4*)(hfrag + (w * 32 + lane) * 4) = hf;
        }
        __syncthreads();   // h-fragments ready for next step
    }
}

// ---------------------------------------------------------------------------
extern "C" void kernel_launch(void* const* d_in, const int* in_sizes, int n_in,
                              void* d_out, int out_size)
{
    // Resolve inputs by element count (robust to metadata ordering).
    int iSeq = -1, iLen = -1, iAtt = -1, iW[3] = {-1, -1, -1};
    int nw = 0;
    for (int i = 0; i < n_in; ++i) {
        int s = in_sizes[i];
        if      (s == 26214400) iSeq = i;
        else if (s == 1024)     iLen = i;
        else if (s == 204800)   iAtt = i;
        else if (s == 32768 && nw < 3) iW[nw++] = i;
    }
    if (iSeq < 0 || iLen < 0 || iAtt < 0 || nw != 3) {
        iSeq = 0; iLen = 1; iAtt = 2; iW[0] = 3; iW[1] = 4; iW[2] = 5;
    }
    int iWu, iWr, iWc;
    if (iW[0] < iSeq) { iWc = iW[0]; iWr = iW[1]; iWu = iW[2]; }  // alphabetical
    else              { iWu = iW[0]; iWr = iW[1]; iWc = iW[2]; }  // insertion

    const float* seq_emb = (const float*)d_in[iSeq];
    const void*  slen    = d_in[iLen];
    const float* att     = (const float*)d_in[iAtt];
    const float* Wu      = (const float*)d_in[iWu];
    const float* Wr      = (const float*)d_in[iWr];
    const float* Wc      = (const float*)d_in[iWc];
    float*       out     = (float*)d_out;

    const int smem1 = 6 * 32768 + 2 * 8192;   // 212992 B
    const int smem2 = 8192 + 98304;           // 106496 B
    cudaFuncSetAttribute(proj_kernel, cudaFuncAttributeMaxDynamicSharedMemorySize, smem1);
    cudaFuncSetAttribute(rec_kernel,  cudaFuncAttributeMaxDynamicSharedMemorySize, smem2);

    proj_kernel<<<148, 256, smem1>>>(seq_emb, Wu, Wr, Wc);
    rec_kernel<<<128, 256, smem2>>>(att, slen, Wu, Wr, Wc, out);
}

// round 12
// speedup vs baseline: 1.4903x; 1.1594x over previous
#include <cuda_runtime.h>
#include <cuda_bf16.h>
#include <cstdint>

#define B_ 1024
#define T_ 200

typedef unsigned long long ull;
typedef unsigned int uint32;

// Scratch for x-projections: [3][T][B][128] fp32 (static device global, allowed).
__device__ float g_proj[(size_t)3 * T_ * B_ * 128];

// HW tanh (MUFU.TANH, sm_75+; base PTX feature).
__device__ __forceinline__ float tanh_hw(float x) {
    float t; asm("tanh.approx.f32 %0, %1;" : "=f"(t) : "f"(x)); return t;
}
__device__ __forceinline__ float sig_hw(float x) {
    return 0.5f * tanh_hw(0.5f * x) + 0.5f;
}

__device__ __forceinline__ uint32 pk_bf16(float a, float b) {
    return (uint32)__bfloat16_as_ushort(__float2bfloat16(a)) |
           ((uint32)__bfloat16_as_ushort(__float2bfloat16(b)) << 16);
}
__device__ __forceinline__ float bf16hi_res(float v, float& hi) {
    __nv_bfloat16 h = __float2bfloat16(v);
    hi = __bfloat162float(h);
    return v - hi;
}
__device__ __forceinline__ void mma_bf16(float& c0, float& c1, float& c2, float& c3,
                                         uint32 a0, uint32 a1, uint32 a2, uint32 a3,
                                         uint32 b0, uint32 b1) {
    asm volatile(
        "mma.sync.aligned.m16n8k16.row.col.f32.bf16.bf16.f32 "
        "{%0,%1,%2,%3}, {%4,%5,%6,%7}, {%8,%9}, {%0,%1,%2,%3};"
        : "+f"(c0), "+f"(c1), "+f"(c2), "+f"(c3)
        : "r"(a0), "r"(a1), "r"(a2), "r"(a3), "r"(b0), "r"(b1));
}

// ---------------------------------------------------------------------------
// Pass 1 (HMMA): g_proj[m][.][.][:] = X @ Wm_top via bf16-split mma.sync.
// (unchanged from rounds 8-11 — ~246-249us, rel_err 4.9e-6)
// ---------------------------------------------------------------------------
#define SW_OFF(row, word) (((uint32)(row) << 8) + ((((word) ^ (((row) & 7) << 2)) & 63) << 2))
__global__ __launch_bounds__(256, 1) void proj_kernel(
    const float* __restrict__ x,
    const float* __restrict__ Wu, const float* __restrict__ Wr,
    const float* __restrict__ Wc)
{
    extern __shared__ char smc[];
    char* sXh = smc + 196608;
    char* sXl = smc + 204800;
    const int tid  = threadIdx.x;
    const int w    = tid >> 5;
    const int lane = tid & 31;
    const int gr   = lane >> 2;
    const int gc   = lane & 3;
    const int wr   = w >> 2;
    const int wc   = w & 3;
    const int r0   = wr * 16;

    {
        const float* Ws[3] = {Wu, Wr, Wc};
        for (int m = 0; m < 3; ++m) {
            char* hb = smc + m * 32768;
            char* lb = smc + (3 + m) * 32768;
            for (int idx = tid; idx < 16384; idx += 256) {
                int k = idx >> 7, j = idx & 127;
                float v = Ws[m][idx];
                __nv_bfloat16 hbf = __float2bfloat16(v);
                float lres = v - __bfloat162float(hbf);
                uint32 off = SW_OFF(j, k >> 1) + (k & 1) * 2;
                *(__nv_bfloat16*)(hb + off) = hbf;
                *(__nv_bfloat16*)(lb + off) = __float2bfloat16(lres);
            }
        }
    }

    const float4* x4 = (const float4*)x;
    const int ntiles = (B_ * T_) / 32;

    float4 xreg[4];
    int tile = blockIdx.x;
    if (tile < ntiles) {
#pragma unroll
        for (int c = 0; c < 4; ++c) xreg[c] = x4[(size_t)tile * 1024 + tid + c * 256];
    }

    for (; tile < ntiles; tile += gridDim.x) {
        __syncthreads();
#pragma unroll
        for (int c = 0; c < 4; ++c) {
            int f = tid + c * 256;
            int r = f >> 5;
            int wd = (f & 31) * 2;
            float4 v = xreg[c];
            uint32 off = SW_OFF(r, wd);
            *(ull*)(sXh + off) = (ull)pk_bf16(v.x, v.y) | ((ull)pk_bf16(v.z, v.w) << 32);
            float lx = v.x - __bfloat162float(__float2bfloat16(v.x));
            float ly = v.y - __bfloat162float(__float2bfloat16(v.y));
            float lz = v.z - __bfloat162float(__float2bfloat16(v.z));
            float lw = v.w - __bfloat162float(__float2bfloat16(v.w));
            *(ull*)(sXl + off) = (ull)pk_bf16(lx, ly) | ((ull)pk_bf16(lz, lw) << 32);
        }
        __syncthreads();

        int ntile = tile + gridDim.x;
        if (ntile < ntiles) {
#pragma unroll
            for (int c = 0; c < 4; ++c) xreg[c] = x4[(size_t)ntile * 1024 + tid + c * 256];
        }

        float C[12][4];
#pragma unroll
        for (int n = 0; n < 12; ++n)
#pragma unroll
            for (int i = 0; i < 4; ++i) C[n][i] = 0.f;

#pragma unroll
        for (int kt = 0; kt < 8; ++kt) {
            const int kw = kt * 8 + gc;
            const uint32 oA0 = SW_OFF(r0 + gr,     kw);
            const uint32 oA1 = SW_OFF(r0 + gr + 8, kw);
            const uint32 oA2 = SW_OFF(r0 + gr,     kw + 4);
            const uint32 oA3 = SW_OFF(r0 + gr + 8, kw + 4);
            uint32 ah0 = *(const uint32*)(sXh + oA0);
            uint32 ah1 = *(const uint32*)(sXh + oA1);
            uint32 ah2 = *(const uint32*)(sXh + oA2);
            uint32 ah3 = *(const uint32*)(sXh + oA3);
            uint32 al0 = *(const uint32*)(sXl + oA0);
            uint32 al1 = *(const uint32*)(sXl + oA1);
            uint32 al2 = *(const uint32*)(sXl + oA2);
            uint32 al3 = *(const uint32*)(sXl + oA3);
#pragma unroll
            for (int nt = 0; nt < 12; ++nt) {
                int n0 = wc * 96 + nt * 8;
                int m  = n0 >> 7;
                int jb = (n0 & 127) + gr;
                const char* bh = smc + m * 32768;
                const char* bl = smc + (3 + m) * 32768;
                uint32 oB0 = SW_OFF(jb, kw);
                uint32 oB1 = SW_OFF(jb, kw + 4);
                uint32 bh0 = *(const uint32*)(bh + oB0);
                uint32 bh1 = *(const uint32*)(bh + oB1);
                uint32 bl0 = *(const uint32*)(bl + oB0);
                uint32 bl1 = *(const uint32*)(bl + oB1);
                mma_bf16(C[nt][0], C[nt][1], C[nt][2], C[nt][3],
                         ah0, ah1, ah2, ah3, bh0, bh1);
                mma_bf16(C[nt][0], C[nt][1], C[nt][2], C[nt][3],
                         ah0, ah1, ah2, ah3, bl0, bl1);
                mma_bf16(C[nt][0], C[nt][1], C[nt][2], C[nt][3],
                         al0, al1, al2, al3, bh0, bh1);
            }
        }

        const int ridA = tile * 32 + r0 + gr;
        const int ridB = ridA + 8;
        const int bA = ridA / T_, tA = ridA - bA * T_;
        const int bB = ridB / T_, tB = ridB - bB * T_;
#pragma unroll
        for (int nt = 0; nt < 12; ++nt) {
            int cgl = wc * 96 + nt * 8 + gc * 2;
            int m = cgl >> 7, j = cgl & 127;
            float* dA = g_proj + ((size_t)(m * T_ + tA) * B_ + bA) * 128 + j;
            float* dB = g_proj + ((size_t)(m * T_ + tB) * B_ + bB) * 128 + j;
            *(float2*)dA = make_float2(C[nt][0], C[nt][1]);
            *(float2*)dB = make_float2(C[nt][2], C[nt][3]);
        }
    }
}

// ---------------------------------------------------------------------------
// Pass 2 (HMMA recurrence): 128 CTAs x 8 batch rows, 256 threads (8 warps).
// Warp w owns output cols [16w, 16w+16).
// MERGED bf16 split: A rows 0-7 = h_hi, rows 8-15 = h_lo (a1/a3 slots).
// 2 MMAs (B_hi, B_lo) into one accumulator; result row qr = c0 + c2 =
// (hi+lo)(Whi+Wlo) — includes the lo*lo term. 96 MMAs/warp/step (was 144).
// Activations via HW tanh.approx. 2 barriers/step.
// ---------------------------------------------------------------------------
__global__ __launch_bounds__(256, 1) void rec_kernel(
    const float* __restrict__ att,
    const void* __restrict__ slen_raw,
    const float* __restrict__ Wu, const float* __restrict__ Wr,
    const float* __restrict__ Wc,
    float* __restrict__ out)
{
    extern __shared__ char smr[];
    uint32* hfrag = (uint32*)smr;             // [8 kt][32 lane][4 u32]  4096 B
    uint32* sfrag = (uint32*)(smr + 4096);    // [8 kt][32 lane][4 u32]  4096 B
    uint32* blo   = (uint32*)(smr + 8192);    // [48 g][8 kt][32 lane][2 u32] 98304 B
    __shared__ int s_is64;

    const int tid  = threadIdx.x;
    const int w    = tid >> 5;
    const int lane = tid & 31;
    const int qr   = lane >> 2;               // frag row / n-within-tile 0..7
    const int qc   = lane & 3;
    const int row  = blockIdx.x * 8 + qr;     // global batch row
    const int colA = w * 16 + qc * 2;         // output cols colA,colA+1
    const int colB = colA + 8;                //             colB,colB+1

    // ---- build B fragments: hi -> registers, lo -> smem ----
    uint32 bhi[6][8][2];
#pragma unroll
    for (int f = 0; f < 6; ++f) {
        const float* Wsrc = (f < 2) ? Wu : (f < 4 ? Wr : Wc);
        const int n = w * 16 + (f & 1) * 8 + qr;
#pragma unroll
        for (int kt = 0; kt < 8; ++kt) {
            int k = kt * 16 + qc * 2;
            float h00, h01, h10, h11;
            float l00 = bf16hi_res(Wsrc[16384 + k * 128 + n], h00);
            float l01 = bf16hi_res(Wsrc[16384 + (k + 1) * 128 + n], h01);
            float l10 = bf16hi_res(Wsrc[16384 + (k + 8) * 128 + n], h10);
            float l11 = bf16hi_res(Wsrc[16384 + (k + 9) * 128 + n], h11);
            bhi[f][kt][0] = pk_bf16(h00, h01);
            bhi[f][kt][1] = pk_bf16(h10, h11);
            uint32* dst = blo + (((w * 6 + f) * 8 + kt) * 32 + lane) * 2;
            dst[0] = pk_bf16(l00, l01);
            dst[1] = pk_bf16(l10, l11);
        }
    }
    // zero h fragments
    for (int i = tid; i < 1024; i += 256) hfrag[i] = 0u;
    if (tid == 0) {
        const int* a = (const int*)slen_raw;   // int64 detection via high words
        s_is64 = (a[1] == 0 && a[3] == 0 && a[5] == 0 && a[7] == 0) ? 1 : 0;
    }
    __syncthreads();

    int sl;
    if (s_is64) sl = (int)((const long long*)slen_raw)[row];
    else        sl = ((const int*)slen_raw)[row];

    float h0 = 0.f, h1 = 0.f, h2 = 0.f, h3 = 0.f;  // h at (row,colA..+1),(row,colB..+1)

    for (int t = 0; t < T_; ++t) {
        // ---- phase 1: gate MMAs (u: f0,f1 | r: f2,f3), merged split ----
        float Dg[4][4];
#pragma unroll
        for (int f = 0; f < 4; ++f)
#pragma unroll
            for (int i = 0; i < 4; ++i) Dg[f][i] = 0.f;

#pragma unroll
        for (int kt = 0; kt < 8; ++kt) {
            uint4 af = *(const uint4*)(hfrag + (kt * 32 + lane) * 4);  // hi0,hi2,lo0,lo2
#pragma unroll
            for (int f = 0; f < 4; ++f) {
                const uint32* bl = blo + (((w * 6 + f) * 8 + kt) * 32 + lane) * 2;
                uint32 bl0 = bl[0], bl1 = bl[1];
                // A: rows 0-7 = hi (a0,a2), rows 8-15 = lo (a1,a3)
                mma_bf16(Dg[f][0], Dg[f][1], Dg[f][2], Dg[f][3],
                         af.x, af.z, af.y, af.w, bhi[f][kt][0], bhi[f][kt][1]);
                mma_bf16(Dg[f][0], Dg[f][1], Dg[f][2], Dg[f][3],
                         af.x, af.z, af.y, af.w, bl0, bl1);
            }
        }

        // ---- gate finalize: pre = (c0+c2, c1+c3); u = sig; s = sig*h ----
        const float* gp = g_proj + (size_t)t * B_ * 128 + (size_t)row * 128;
        float2 xuA = *(const float2*)(gp + colA);
        float2 xuB = *(const float2*)(gp + colB);
        float2 xrA = *(const float2*)(gp + (size_t)T_ * B_ * 128 + colA);
        float2 xrB = *(const float2*)(gp + (size_t)T_ * B_ * 128 + colB);
        float uA0 = sig_hw(Dg[0][0] + Dg[0][2] + xuA.x);
        float uA1 = sig_hw(Dg[0][1] + Dg[0][3] + xuA.y);
        float uB0 = sig_hw(Dg[1][0] + Dg[1][2] + xuB.x);
        float uB1 = sig_hw(Dg[1][1] + Dg[1][3] + xuB.y);
        float sA0 = sig_hw(Dg[2][0] + Dg[2][2] + xrA.x) * h0;
        float sA1 = sig_hw(Dg[2][1] + Dg[2][3] + xrA.y) * h1;
        float sB0 = sig_hw(Dg[3][0] + Dg[3][2] + xrB.x) * h2;
        float sB1 = sig_hw(Dg[3][1] + Dg[3][3] + xrB.y) * h3;
        {
            float hA0, hA1, hB0, hB1;
            float lA0 = bf16hi_res(sA0, hA0), lA1 = bf16hi_res(sA1, hA1);
            float lB0 = bf16hi_res(sB0, hB0), lB1 = bf16hi_res(sB1, hB1);
            uint4 sf;
            sf.x = pk_bf16(hA0, hA1); sf.y = pk_bf16(hB0, hB1);
            sf.z = pk_bf16(lA0, lA1); sf.w = pk_bf16(lB0, lB1);
            *(uint4*)(sfrag + (w * 32 + lane) * 4) = sf;
        }
        __syncthreads();   // s-fragments ready

        // ---- phase 2: candidate MMAs (f4,f5), merged split ----
        float Dc[2][4];
#pragma unroll
        for (int f = 0; f < 2; ++f)
#pragma unroll
            for (int i = 0; i < 4; ++i) Dc[f][i] = 0.f;

#pragma unroll
        for (int kt = 0; kt < 8; ++kt) {
            uint4 af = *(const uint4*)(sfrag + (kt * 32 + lane) * 4);
#pragma unroll
            for (int f = 0; f < 2; ++f) {
                const uint32* bl = blo + (((w * 6 + 4 + f) * 8 + kt) * 32 + lane) * 2;
                uint32 bl0 = bl[0], bl1 = bl[1];
                mma_bf16(Dc[f][0], Dc[f][1], Dc[f][2], Dc[f][3],
                         af.x, af.z, af.y, af.w, bhi[4 + f][kt][0], bhi[4 + f][kt][1]);
                mma_bf16(Dc[f][0], Dc[f][1], Dc[f][2], Dc[f][3],
                         af.x, af.z, af.y, af.w, bl0, bl1);
            }
        }

        // ---- update ----
        float2 xcA = *(const float2*)(gp + (size_t)2 * T_ * B_ * 128 + colA);
        float2 xcB = *(const float2*)(gp + (size_t)2 * T_ * B_ * 128 + colB);
        float av = att[(size_t)row * T_ + t];
        bool live = (t < sl);
        {
            float htA0 = tanh_hw(Dc[0][0] + Dc[0][2] + xcA.x);
            float htA1 = tanh_hw(Dc[0][1] + Dc[0][3] + xcA.y);
            float htB0 = tanh_hw(Dc[1][0] + Dc[1][2] + xcB.x);
            float htB1 = tanh_hw(Dc[1][1] + Dc[1][3] + xcB.y);
            float n0 = h0 + uA0 * av * (htA0 - h0);
            float n1 = h1 + uA1 * av * (htA1 - h1);
            float n2 = h2 + uB0 * av * (htB0 - h2);
            float n3 = h3 + uB1 * av * (htB1 - h3);
            h0 = live ? n0 : h0;
            h1 = live ? n1 : h1;
            h2 = live ? n2 : h2;
            h3 = live ? n3 : h3;
        }
        float* op = out + ((size_t)row * T_ + t) * 128;
        *(float2*)(op + colA) = make_float2(h0, h1);
        *(float2*)(op + colB) = make_float2(h2, h3);
        {
            float hA0, hA1, hB0, hB1;
            float lA0 = bf16hi_res(h0, hA0), lA1 = bf16hi_res(h1, hA1);
            float lB0 = bf16hi_res(h2, hB0), lB1 = bf16hi_res(h3, hB1);
            uint4 hf;
            hf.x = pk_bf16(hA0, hA1); hf.y = pk_bf16(hB0, hB1);
            hf.z = pk_bf16(lA0, lA1); hf.w = pk_bf16(lB0, lB1);
            *(uint4*)(hfrag + (w * 32 + lane) * 4) = hf;
        }
        __syncthreads();   // h-fragments ready for next step
    }
}

// ---------------------------------------------------------------------------
extern "C" void kernel_launch(void* const* d_in, const int* in_sizes, int n_in,
                              void* d_out, int out_size)
{
    // Resolve inputs by element count (robust to metadata ordering).
    int iSeq = -1, iLen = -1, iAtt = -1, iW[3] = {-1, -1, -1};
    int nw = 0;
    for (int i = 0; i < n_in; ++i) {
        int s = in_sizes[i];
        if      (s == 26214400) iSeq = i;
        else if (s == 1024)     iLen = i;
        else if (s == 204800)   iAtt = i;
        else if (s == 32768 && nw < 3) iW[nw++] = i;
    }
    if (iSeq < 0 || iLen < 0 || iAtt < 0 || nw != 3) {
        iSeq = 0; iLen = 1; iAtt = 2; iW[0] = 3; iW[1] = 4; iW[2] = 5;
    }
    int iWu, iWr, iWc;
    if (iW[0] < iSeq) { iWc = iW[0]; iWr = iW[1]; iWu = iW[2]; }  // alphabetical
    else              { iWu = iW[0]; iWr = iW[1]; iWc = iW[2]; }  // insertion

    const float* seq_emb = (const float*)d_in[iSeq];
    const void*  slen    = d_in[iLen];
    const float* att     = (const float*)d_in[iAtt];
    const float* Wu      = (const float*)d_in[iWu];
    const float* Wr      = (const float*)d_in[iWr];
    const float* Wc      = (const float*)d_in[iWc];
    float*       out     = (float*)d_out;

    const int smem1 = 6 * 32768 + 2 * 8192;   // 212992 B
    const int smem2 = 8192 + 98304;           // 106496 B
    cudaFuncSetAttribute(proj_kernel, cudaFuncAttributeMaxDynamicSharedMemorySize, smem1);
    cudaFuncSetAttribute(rec_kernel,  cudaFuncAttributeMaxDynamicSharedMemorySize, smem2);

    proj_kernel<<<148, 256, smem1>>>(seq_emb, Wu, Wr, Wc);
    rec_kernel<<<128, 256, smem2>>>(att, slen, Wu, Wr, Wc, out);
}